// round 13
// baseline (speedup 1.0000x reference)
#include <cuda_runtime.h>
#include <cuda_fp16.h>
#include <mma.h>
#include <math.h>
#include <cstdint>

#define MAXN 50000
#define MAXE 1600000

using namespace nvcuda;

// ---------------- device scratch (zero-initialized at module load) ----------
__device__ __align__(16) __half2 g_h1h[MAXN * 32]; // layer1 h, fp16 [N,64]
__device__ __align__(16) float g_as1[MAXN * 8];
__device__ __align__(16) float g_ad1[MAXN * 8];
__device__ __align__(16) float g_h1p[MAXN * 64];   // layer1 out (bias+elu)
__device__ __align__(16) __half2 g_h2h[MAXN * 32]; // layer2 h, fp16
__device__ __align__(16) float g_as2[MAXN];
__device__ __align__(16) float g_ad2[MAXN];
__device__ __align__(16) __half g_wh[256 * 64];    // W1 fp16 [256][64]
__device__ int g_cnt [MAXN];                        // zeroed at END of each call
__device__ int g_cur [MAXN];                        // zeroed at END of each call
__device__ int g_offs[MAXN + 1];
__device__ int g_bsum[64];
__device__ __align__(16) int g_ebuf[MAXE];
__device__ int g_is64;

// ---------------- edge dtype detect -----------------------------------------
__global__ void detect_kernel(const int* __restrict__ ei32, int E) {
    __shared__ int s_or;
    if (threadIdx.x == 0) s_or = 0;
    __syncthreads();
    int acc = 0;
    int nsamp = (E < 4096) ? E : 4096;
    for (int j = threadIdx.x; j < nsamp; j += blockDim.x)
        acc |= ei32[2 * j + 1];
    atomicOr(&s_or, acc);
    __syncthreads();
    if (threadIdx.x == 0) g_is64 = (s_or == 0) ? 1 : 0;
}

// counters consumed this call; zero them for the next call (runs overlapped)
__global__ void reset_kernel(int N) {
    int i = blockIdx.x * blockDim.x + threadIdx.x;
    if (i < N) { g_cnt[i] = 0; g_cur[i] = 0; }
}

// ---------------- W1 -> fp16 -------------------------------------------------
__global__ void wconv_kernel(const float* __restrict__ W1) {
    int i = blockIdx.x * blockDim.x + threadIdx.x;   // 16384
    g_wh[i] = __float2half_rn(W1[i]);
}

__global__ void count_kernel(const void* __restrict__ ei, int E, int N) {
    int i = blockIdx.x * blockDim.x + threadIdx.x;
    if (i >= E) return;
    int d = g_is64 ? (int)((const long long*)ei)[E + i]
                   : ((const int*)ei)[E + i];
    if ((unsigned)d < (unsigned)N) atomicAdd(&g_cnt[d], 1);
}

// ---------------- layer 1 GEMM via WMMA fp16 (HMMA) -------------------------
#define WS_LD 72
#define XS_LD 264
#define OS_LD 72
__global__ void __launch_bounds__(256) gemm1_wmma_kernel(
        const float* __restrict__ x,
        const float* __restrict__ att_s, const float* __restrict__ att_d,
        int N) {
    extern __shared__ char smem[];
    __half* Wsm = (__half*)smem;                     // [256][WS_LD]
    __half* xs  = (__half*)(smem + 36864);           // [128][XS_LD]
    float*  osm = (float*)(smem + 36864);            // aliases xs

    int tid = threadIdx.x;
    int wid = tid >> 5;
    int r0 = blockIdx.x * 128;

    #pragma unroll
    for (int i = 0; i < 8; i++) {
        int idx = tid + i * 256;
        int row = idx >> 3, q = idx & 7;
        *(uint4*)&Wsm[row * WS_LD + q * 8] = ((const uint4*)g_wh)[idx];
    }
    #pragma unroll
    for (int it = 0; it < 32; it++) {
        int idx = tid + it * 256;
        int row = idx >> 6, f4 = idx & 63;
        int grow = r0 + row;
        float4 v = make_float4(0.f, 0.f, 0.f, 0.f);
        if (grow < N) v = ((const float4*)x)[(size_t)grow * 64 + f4];
        __half2 h01 = __floats2half2_rn(v.x, v.y);
        __half2 h23 = __floats2half2_rn(v.z, v.w);
        *(uint2*)&xs[row * XS_LD + f4 * 4] =
            make_uint2(*(uint32_t*)&h01, *(uint32_t*)&h23);
    }
    __syncthreads();

    wmma::fragment<wmma::accumulator, 16, 16, 16, float> c[4];
    #pragma unroll
    for (int n = 0; n < 4; n++) wmma::fill_fragment(c[n], 0.f);

    #pragma unroll
    for (int k16 = 0; k16 < 16; k16++) {
        wmma::fragment<wmma::matrix_a, 16, 16, 16, __half, wmma::row_major> a;
        wmma::load_matrix_sync(a, &xs[wid * 16 * XS_LD + k16 * 16], XS_LD);
        #pragma unroll
        for (int n = 0; n < 4; n++) {
            wmma::fragment<wmma::matrix_b, 16, 16, 16, __half, wmma::row_major> b;
            wmma::load_matrix_sync(b, &Wsm[k16 * 16 * WS_LD + n * 16], WS_LD);
            wmma::mma_sync(c[n], a, b, c[n]);
        }
    }

    __syncthreads();
    #pragma unroll
    for (int n = 0; n < 4; n++)
        wmma::store_matrix_sync(&osm[wid * 16 * OS_LD + n * 16], c[n], OS_LD,
                                wmma::mem_row_major);
    __syncthreads();

    int row = tid >> 1, half = tid & 1;
    int grow = r0 + row;
    if (grow < N) {
        const float* orow = &osm[row * OS_LD + half * 32];
        #pragma unroll
        for (int q = 0; q < 4; q++) {
            __half2 hh[4];
            #pragma unroll
            for (int p = 0; p < 4; p++)
                hh[p] = __floats2half2_rn(orow[q * 8 + p * 2], orow[q * 8 + p * 2 + 1]);
            *(uint4*)(&g_h1h[(size_t)grow * 32 + half * 16 + q * 4]) = *(uint4*)hh;
        }
        #pragma unroll
        for (int hh = 0; hh < 4; hh++) {
            int h = half * 4 + hh;
            float as = 0.f, ad = 0.f;
            #pragma unroll
            for (int j = 0; j < 8; j++) {
                float cv = orow[hh * 8 + j];
                as = fmaf(cv, __ldg(&att_s[h * 8 + j]), as);
                ad = fmaf(cv, __ldg(&att_d[h * 8 + j]), ad);
            }
            g_as1[grow * 8 + h] = as;
            g_ad1[grow * 8 + h] = ad;
        }
    }
}

// ---------------- scan ------------------------------------------------------
__global__ void scan_block_kernel(int N) {
    __shared__ int wsum[32];
    int tid = threadIdx.x, lane = tid & 31, wid = tid >> 5;
    int i = blockIdx.x * 1024 + tid;
    int v = (i < N) ? g_cnt[i] : 0;
    int sc = v;
    #pragma unroll
    for (int o = 1; o < 32; o <<= 1) {
        int t = __shfl_up_sync(0xffffffffu, sc, o);
        if (lane >= o) sc += t;
    }
    if (lane == 31) wsum[wid] = sc;
    __syncthreads();
    if (wid == 0) {
        int s = wsum[lane];
        #pragma unroll
        for (int o = 1; o < 32; o <<= 1) {
            int t = __shfl_up_sync(0xffffffffu, s, o);
            if (lane >= o) s += t;
        }
        wsum[lane] = s;
    }
    __syncthreads();
    int add = (wid > 0) ? wsum[wid - 1] : 0;
    if (i < N) g_offs[i] = add + sc - v;
    if (tid == 0) g_bsum[blockIdx.x] = wsum[31];
}

__global__ void scan_add_kernel(int N, int nb) {
    __shared__ int prefix;
    int b = blockIdx.x;
    int lane = threadIdx.x & 31;
    if (threadIdx.x < 32) {
        int acc = 0;
        for (int j = lane; j < b; j += 32) acc += g_bsum[j];
        #pragma unroll
        for (int o = 16; o >= 1; o >>= 1) acc += __shfl_xor_sync(0xffffffffu, acc, o);
        if (lane == 0) prefix = acc;
    }
    __syncthreads();
    int i = b * 1024 + threadIdx.x;
    if (i < N) g_offs[i] += prefix;
    if (b == nb - 1 && threadIdx.x == 0) g_offs[N] = prefix + g_bsum[b];
}

__global__ void scatter_kernel(const void* __restrict__ ei, int E, int N) {
    int i = blockIdx.x * blockDim.x + threadIdx.x;
    if (i >= E) return;
    int s, d;
    if (g_is64) {
        const long long* e64 = (const long long*)ei;
        s = (int)e64[i]; d = (int)e64[E + i];
    } else {
        const int* e32 = (const int*)ei;
        s = e32[i]; d = e32[E + i];
    }
    if ((unsigned)d < (unsigned)N) {
        int p = atomicAdd(&g_cur[d], 1);
        g_ebuf[g_offs[d] + p] = s;
    }
}

#define LRELU(e) ((e) > 0.f ? (e) : 0.2f * (e))

// ---------------- layer 1 aggregation: 2 warps per dst ----------------------
__global__ void __launch_bounds__(256) agg1_kernel(const float* __restrict__ bias1, int N) {
    __shared__ float s_den[4][32], s_ax[4][32], s_ay[4][32];
    int tid = threadIdx.x, wid = tid >> 5, lane = tid & 31;
    int dl = wid >> 1, sub = wid & 1;
    int dst = blockIdx.x * 4 + dl;
    int head = lane >> 2;

    float ad = 0.f; int beg = 0, end = 0;
    if (dst < N) {
        ad = g_ad1[dst * 8 + head];
        int b = g_offs[dst], e = g_offs[dst + 1];
        int half = (e - b + 1) >> 1;
        beg = sub ? b + half : b;
        end = sub ? e : b + half;
    }

    float den = 0.f, ax = 0.f, ay = 0.f;
    int i = beg;
    for (; i < end && (i & 3); i++) {
        int s = __ldg(&g_ebuf[i]);
        float w = __expf(LRELU(__ldg(&g_as1[s * 8 + head]) + ad));
        float2 hv = __half22float2(__ldg(&g_h1h[(size_t)s * 32 + lane]));
        den += w; ax = fmaf(w, hv.x, ax); ay = fmaf(w, hv.y, ay);
    }
    for (; i + 8 <= end; i += 8) {
        int4 sa = *(const int4*)&g_ebuf[i];
        int4 sb = *(const int4*)&g_ebuf[i + 4];
        float e0 = __ldg(&g_as1[sa.x * 8 + head]);
        float e1 = __ldg(&g_as1[sa.y * 8 + head]);
        float e2 = __ldg(&g_as1[sa.z * 8 + head]);
        float e3 = __ldg(&g_as1[sa.w * 8 + head]);
        float e4 = __ldg(&g_as1[sb.x * 8 + head]);
        float e5 = __ldg(&g_as1[sb.y * 8 + head]);
        float e6 = __ldg(&g_as1[sb.z * 8 + head]);
        float e7 = __ldg(&g_as1[sb.w * 8 + head]);
        __half2 q0 = __ldg(&g_h1h[(size_t)sa.x * 32 + lane]);
        __half2 q1 = __ldg(&g_h1h[(size_t)sa.y * 32 + lane]);
        __half2 q2 = __ldg(&g_h1h[(size_t)sa.z * 32 + lane]);
        __half2 q3 = __ldg(&g_h1h[(size_t)sa.w * 32 + lane]);
        __half2 q4 = __ldg(&g_h1h[(size_t)sb.x * 32 + lane]);
        __half2 q5 = __ldg(&g_h1h[(size_t)sb.y * 32 + lane]);
        __half2 q6 = __ldg(&g_h1h[(size_t)sb.z * 32 + lane]);
        __half2 q7 = __ldg(&g_h1h[(size_t)sb.w * 32 + lane]);
        float w0 = __expf(LRELU(e0 + ad)), w1 = __expf(LRELU(e1 + ad));
        float w2 = __expf(LRELU(e2 + ad)), w3 = __expf(LRELU(e3 + ad));
        float w4 = __expf(LRELU(e4 + ad)), w5 = __expf(LRELU(e5 + ad));
        float w6 = __expf(LRELU(e6 + ad)), w7 = __expf(LRELU(e7 + ad));
        den += ((w0 + w1) + (w2 + w3)) + ((w4 + w5) + (w6 + w7));
        float2 f0 = __half22float2(q0), f1 = __half22float2(q1);
        float2 f2 = __half22float2(q2), f3 = __half22float2(q3);
        float2 f4 = __half22float2(q4), f5 = __half22float2(q5);
        float2 f6 = __half22float2(q6), f7 = __half22float2(q7);
        ax = fmaf(w0, f0.x, ax); ay = fmaf(w0, f0.y, ay);
        ax = fmaf(w1, f1.x, ax); ay = fmaf(w1, f1.y, ay);
        ax = fmaf(w2, f2.x, ax); ay = fmaf(w2, f2.y, ay);
        ax = fmaf(w3, f3.x, ax); ay = fmaf(w3, f3.y, ay);
        ax = fmaf(w4, f4.x, ax); ay = fmaf(w4, f4.y, ay);
        ax = fmaf(w5, f5.x, ax); ay = fmaf(w5, f5.y, ay);
        ax = fmaf(w6, f6.x, ax); ay = fmaf(w6, f6.y, ay);
        ax = fmaf(w7, f7.x, ax); ay = fmaf(w7, f7.y, ay);
    }
    for (; i + 4 <= end; i += 4) {
        int4 ss = *(const int4*)&g_ebuf[i];
        float e0 = __ldg(&g_as1[ss.x * 8 + head]);
        float e1 = __ldg(&g_as1[ss.y * 8 + head]);
        float e2 = __ldg(&g_as1[ss.z * 8 + head]);
        float e3 = __ldg(&g_as1[ss.w * 8 + head]);
        __half2 q0 = __ldg(&g_h1h[(size_t)ss.x * 32 + lane]);
        __half2 q1 = __ldg(&g_h1h[(size_t)ss.y * 32 + lane]);
        __half2 q2 = __ldg(&g_h1h[(size_t)ss.z * 32 + lane]);
        __half2 q3 = __ldg(&g_h1h[(size_t)ss.w * 32 + lane]);
        float w0 = __expf(LRELU(e0 + ad)), w1 = __expf(LRELU(e1 + ad));
        float w2 = __expf(LRELU(e2 + ad)), w3 = __expf(LRELU(e3 + ad));
        den += (w0 + w1) + (w2 + w3);
        float2 f0 = __half22float2(q0), f1 = __half22float2(q1);
        float2 f2 = __half22float2(q2), f3 = __half22float2(q3);
        ax = fmaf(w0, f0.x, ax); ay = fmaf(w0, f0.y, ay);
        ax = fmaf(w1, f1.x, ax); ay = fmaf(w1, f1.y, ay);
        ax = fmaf(w2, f2.x, ax); ay = fmaf(w2, f2.y, ay);
        ax = fmaf(w3, f3.x, ax); ay = fmaf(w3, f3.y, ay);
    }
    for (; i < end; i++) {
        int s = __ldg(&g_ebuf[i]);
        float w = __expf(LRELU(__ldg(&g_as1[s * 8 + head]) + ad));
        float2 hv = __half22float2(__ldg(&g_h1h[(size_t)s * 32 + lane]));
        den += w; ax = fmaf(w, hv.x, ax); ay = fmaf(w, hv.y, ay);
    }

    if (sub) { s_den[dl][lane] = den; s_ax[dl][lane] = ax; s_ay[dl][lane] = ay; }
    __syncthreads();
    if (!sub && dst < N) {
        den += s_den[dl][lane]; ax += s_ax[dl][lane]; ay += s_ay[dl][lane];
        float inv = 1.f / (den + 1e-16f);
        int c0 = lane * 2;
        float v0 = fmaf(ax, inv, bias1[c0]);
        float v1 = fmaf(ay, inv, bias1[c0 + 1]);
        v0 = (v0 > 0.f) ? v0 : expm1f(v0);
        v1 = (v1 > 0.f) ? v1 : expm1f(v1);
        ((float2*)g_h1p)[(size_t)dst * 32 + lane] = make_float2(v0, v1);
    }
}

// ---------------- layer 2 GEMM ----------------------------------------------
__global__ void gemm2_kernel(const float* __restrict__ W2,
                             const float* __restrict__ att_s2, const float* __restrict__ att_d2,
                             int N) {
    __shared__ float Ws[64 * 64];
    __shared__ float xs[32 * 64];
    int tid = threadIdx.x;

    float4* Ws4 = (float4*)Ws;
    const float4* Wg4 = (const float4*)W2;
    #pragma unroll
    for (int i = 0; i < 4; i++) Ws4[tid + i * 256] = Wg4[tid + i * 256];

    int r0 = blockIdx.x * 32;
    float4* xs4 = (float4*)xs;
    const float4* xg4 = (const float4*)(g_h1p + (size_t)r0 * 64);
    int rows = N - r0; if (rows > 32) rows = 32;
    int nf4 = rows * 16;
    #pragma unroll
    for (int i = 0; i < 2; i++) {
        int idx = tid + i * 256;
        xs4[idx] = (idx < nf4) ? xg4[idx] : make_float4(0.f, 0.f, 0.f, 0.f);
    }
    __syncthreads();

    int r = tid >> 3, cg = tid & 7;
    float acc[8];
    #pragma unroll
    for (int j = 0; j < 8; j++) acc[j] = 0.f;
    const float* xr = xs + r * 64;
    #pragma unroll 8
    for (int k = 0; k < 64; k++) {
        float xv = xr[k];
        float4 w0 = Ws4[k * 16 + cg * 2];
        float4 w1 = Ws4[k * 16 + cg * 2 + 1];
        acc[0] = fmaf(xv, w0.x, acc[0]); acc[1] = fmaf(xv, w0.y, acc[1]);
        acc[2] = fmaf(xv, w0.z, acc[2]); acc[3] = fmaf(xv, w0.w, acc[3]);
        acc[4] = fmaf(xv, w1.x, acc[4]); acc[5] = fmaf(xv, w1.y, acc[5]);
        acc[6] = fmaf(xv, w1.z, acc[6]); acc[7] = fmaf(xv, w1.w, acc[7]);
    }

    float ps = 0.f, pd = 0.f;
    #pragma unroll
    for (int j = 0; j < 8; j++) {
        ps = fmaf(acc[j], att_s2[cg * 8 + j], ps);
        pd = fmaf(acc[j], att_d2[cg * 8 + j], pd);
    }
    #pragma unroll
    for (int o = 4; o >= 1; o >>= 1) {
        ps += __shfl_down_sync(0xffffffffu, ps, o);
        pd += __shfl_down_sync(0xffffffffu, pd, o);
    }

    int row = r0 + r;
    if (row < N) {
        __half2 hh[4];
        #pragma unroll
        for (int cp = 0; cp < 4; cp++)
            hh[cp] = __floats2half2_rn(acc[cp * 2], acc[cp * 2 + 1]);
        *(uint4*)(&g_h2h[(size_t)row * 32 + cg * 4]) = *(uint4*)hh;
        if (cg == 0) { g_as2[row] = ps; g_ad2[row] = pd; }
    }
}

// ---------------- layer 2 aggregation: 2 warps per dst + log_softmax --------
__global__ void __launch_bounds__(256) agg2_kernel(const float* __restrict__ bias2,
                                                   float* __restrict__ out, int N) {
    __shared__ float s_den[4][32], s_ax[4][32], s_ay[4][32];
    int tid = threadIdx.x, wid = tid >> 5, lane = tid & 31;
    int dl = wid >> 1, sub = wid & 1;
    int dst = blockIdx.x * 4 + dl;

    float ad = 0.f; int beg = 0, end = 0;
    if (dst < N) {
        ad = g_ad2[dst];
        int b = g_offs[dst], e = g_offs[dst + 1];
        int half = (e - b + 1) >> 1;
        beg = sub ? b + half : b;
        end = sub ? e : b + half;
    }

    float den = 0.f, ax = 0.f, ay = 0.f;
    int i = beg;
    for (; i < end && (i & 3); i++) {
        int s = __ldg(&g_ebuf[i]);
        float w = __expf(LRELU(__ldg(&g_as2[s]) + ad));
        float2 hv = __half22float2(__ldg(&g_h2h[(size_t)s * 32 + lane]));
        den += w; ax = fmaf(w, hv.x, ax); ay = fmaf(w, hv.y, ay);
    }
    for (; i + 8 <= end; i += 8) {
        int4 sa = *(const int4*)&g_ebuf[i];
        int4 sb = *(const int4*)&g_ebuf[i + 4];
        float e0 = __ldg(&g_as2[sa.x]);
        float e1 = __ldg(&g_as2[sa.y]);
        float e2 = __ldg(&g_as2[sa.z]);
        float e3 = __ldg(&g_as2[sa.w]);
        float e4 = __ldg(&g_as2[sb.x]);
        float e5 = __ldg(&g_as2[sb.y]);
        float e6 = __ldg(&g_as2[sb.z]);
        float e7 = __ldg(&g_as2[sb.w]);
        __half2 q0 = __ldg(&g_h2h[(size_t)sa.x * 32 + lane]);
        __half2 q1 = __ldg(&g_h2h[(size_t)sa.y * 32 + lane]);
        __half2 q2 = __ldg(&g_h2h[(size_t)sa.z * 32 + lane]);
        __half2 q3 = __ldg(&g_h2h[(size_t)sa.w * 32 + lane]);
        __half2 q4 = __ldg(&g_h2h[(size_t)sb.x * 32 + lane]);
        __half2 q5 = __ldg(&g_h2h[(size_t)sb.y * 32 + lane]);
        __half2 q6 = __ldg(&g_h2h[(size_t)sb.z * 32 + lane]);
        __half2 q7 = __ldg(&g_h2h[(size_t)sb.w * 32 + lane]);
        float w0 = __expf(LRELU(e0 + ad)), w1 = __expf(LRELU(e1 + ad));
        float w2 = __expf(LRELU(e2 + ad)), w3 = __expf(LRELU(e3 + ad));
        float w4 = __expf(LRELU(e4 + ad)), w5 = __expf(LRELU(e5 + ad));
        float w6 = __expf(LRELU(e6 + ad)), w7 = __expf(LRELU(e7 + ad));
        den += ((w0 + w1) + (w2 + w3)) + ((w4 + w5) + (w6 + w7));
        float2 f0 = __half22float2(q0), f1 = __half22float2(q1);
        float2 f2 = __half22float2(q2), f3 = __half22float2(q3);
        float2 f4 = __half22float2(q4), f5 = __half22float2(q5);
        float2 f6 = __half22float2(q6), f7 = __half22float2(q7);
        ax = fmaf(w0, f0.x, ax); ay = fmaf(w0, f0.y, ay);
        ax = fmaf(w1, f1.x, ax); ay = fmaf(w1, f1.y, ay);
        ax = fmaf(w2, f2.x, ax); ay = fmaf(w2, f2.y, ay);
        ax = fmaf(w3, f3.x, ax); ay = fmaf(w3, f3.y, ay);
        ax = fmaf(w4, f4.x, ax); ay = fmaf(w4, f4.y, ay);
        ax = fmaf(w5, f5.x, ax); ay = fmaf(w5, f5.y, ay);
        ax = fmaf(w6, f6.x, ax); ay = fmaf(w6, f6.y, ay);
        ax = fmaf(w7, f7.x, ax); ay = fmaf(w7, f7.y, ay);
    }
    for (; i + 4 <= end; i += 4) {
        int4 ss = *(const int4*)&g_ebuf[i];
        float e0 = __ldg(&g_as2[ss.x]);
        float e1 = __ldg(&g_as2[ss.y]);
        float e2 = __ldg(&g_as2[ss.z]);
        float e3 = __ldg(&g_as2[ss.w]);
        __half2 q0 = __ldg(&g_h2h[(size_t)ss.x * 32 + lane]);
        __half2 q1 = __ldg(&g_h2h[(size_t)ss.y * 32 + lane]);
        __half2 q2 = __ldg(&g_h2h[(size_t)ss.z * 32 + lane]);
        __half2 q3 = __ldg(&g_h2h[(size_t)ss.w * 32 + lane]);
        float w0 = __expf(LRELU(e0 + ad)), w1 = __expf(LRELU(e1 + ad));
        float w2 = __expf(LRELU(e2 + ad)), w3 = __expf(LRELU(e3 + ad));
        den += (w0 + w1) + (w2 + w3);
        float2 f0 = __half22float2(q0), f1 = __half22float2(q1);
        float2 f2 = __half22float2(q2), f3 = __half22float2(q3);
        ax = fmaf(w0, f0.x, ax); ay = fmaf(w0, f0.y, ay);
        ax = fmaf(w1, f1.x, ax); ay = fmaf(w1, f1.y, ay);
        ax = fmaf(w2, f2.x, ax); ay = fmaf(w2, f2.y, ay);
        ax = fmaf(w3, f3.x, ax); ay = fmaf(w3, f3.y, ay);
    }
    for (; i < end; i++) {
        int s = __ldg(&g_ebuf[i]);
        float w = __expf(LRELU(__ldg(&g_as2[s]) + ad));
        float2 hv = __half22float2(__ldg(&g_h2h[(size_t)s * 32 + lane]));
        den += w; ax = fmaf(w, hv.x, ax); ay = fmaf(w, hv.y, ay);
    }

    if (sub) { s_den[dl][lane] = den; s_ax[dl][lane] = ax; s_ay[dl][lane] = ay; }
    __syncthreads();
    if (!sub && dst < N) {
        den += s_den[dl][lane]; ax += s_ax[dl][lane]; ay += s_ay[dl][lane];
        float inv = 1.f / (den + 1e-16f);
        int c0 = lane * 2;
        float v0 = fmaf(ax, inv, bias2[c0]);
        float v1 = fmaf(ay, inv, bias2[c0 + 1]);

        float m = fmaxf(v0, v1);
        #pragma unroll
        for (int o = 16; o >= 1; o >>= 1) m = fmaxf(m, __shfl_xor_sync(0xffffffffu, m, o));
        float se = __expf(v0 - m) + __expf(v1 - m);
        #pragma unroll
        for (int o = 16; o >= 1; o >>= 1) se += __shfl_xor_sync(0xffffffffu, se, o);
        float lse = m + logf(se);

        ((float2*)out)[(size_t)dst * 32 + lane] = make_float2(v0 - lse, v1 - lse);
    }
}

// ---------------- launch ----------------------------------------------------
extern "C" void kernel_launch(void* const* d_in, const int* in_sizes, int n_in,
                              void* d_out, int out_size) {
    const float* x      = (const float*)d_in[0];
    const void*  ei     = d_in[1];
    const float* W1     = (const float*)d_in[2];
    const float* atts1  = (const float*)d_in[3];
    const float* attd1  = (const float*)d_in[4];
    const float* bias1  = (const float*)d_in[5];
    const float* W2     = (const float*)d_in[6];
    const float* atts2  = (const float*)d_in[7];
    const float* attd2  = (const float*)d_in[8];
    const float* bias2  = (const float*)d_in[9];
    float* out = (float*)d_out;

    int N = in_sizes[0] / 256;
    int E = in_sizes[1] / 2;
    int nb = (N + 1023) / 1024;

    static cudaStream_t s2 = nullptr;
    static cudaEvent_t evRoot = nullptr, evG = nullptr, evS = nullptr, evR = nullptr;
    if (s2 == nullptr) {
        cudaStreamCreateWithFlags(&s2, cudaStreamNonBlocking);
        cudaEventCreateWithFlags(&evRoot, cudaEventDisableTiming);
        cudaEventCreateWithFlags(&evG, cudaEventDisableTiming);
        cudaEventCreateWithFlags(&evS, cudaEventDisableTiming);
        cudaEventCreateWithFlags(&evR, cudaEventDisableTiming);
        cudaFuncSetAttribute(gemm1_wmma_kernel,
                             cudaFuncAttributeMaxDynamicSharedMemorySize, 104448);
    }

    // fork: GEMM chain on s2, CSR chain on the main stream.
    // counters (g_cnt/g_cur) are zero on entry: zero-initialized globals on
    // the first call, reset at the END of each previous call thereafter.
    cudaEventRecord(evRoot, 0);
    cudaStreamWaitEvent(s2, evRoot, 0);

    wconv_kernel     <<<64, 256, 0, s2>>>(W1);
    gemm1_wmma_kernel<<<(N + 127) / 128, 256, 104448, s2>>>(x, atts1, attd1, N);
    cudaEventRecord(evG, s2);

    detect_kernel    <<<1, 256>>>((const int*)ei, E);
    count_kernel     <<<(E + 255) / 256, 256>>>(ei, E, N);
    scan_block_kernel<<<nb, 1024>>>(N);
    scan_add_kernel  <<<nb, 1024>>>(N, nb);
    scatter_kernel   <<<(E + 255) / 256, 256>>>(ei, E, N);
    cudaEventRecord(evS, 0);

    // counter reset for the next call — overlapped with the agg/gemm2 tail
    cudaStreamWaitEvent(s2, evS, 0);
    reset_kernel<<<(N + 255) / 256, 256, 0, s2>>>(N);
    cudaEventRecord(evR, s2);

    // join: agg1 needs both chains
    cudaStreamWaitEvent(0, evG, 0);
    agg1_kernel <<<(N + 3) / 4, 256>>>(bias1, N);
    gemm2_kernel<<<(N + 31) / 32, 256>>>(W2, atts2, attd2, N);
    agg2_kernel <<<(N + 3) / 4, 256>>>(bias2, out, N);

    // rejoin s2 before capture ends
    cudaStreamWaitEvent(0, evR, 0);
}

// round 14
// speedup vs baseline: 1.0638x; 1.0638x over previous
#include <cuda_runtime.h>
#include <cuda_fp16.h>
#include <mma.h>
#include <math.h>
#include <cstdint>

#define MAXN 50000
#define MAXE 1600000

using namespace nvcuda;

// ---------------- device scratch (zero-initialized at module load) ----------
__device__ __align__(16) __half2 g_h1h[MAXN * 32]; // layer1 h, fp16 [N,64]
__device__ __align__(16) float g_as1[MAXN * 8];
__device__ __align__(16) float g_ad1[MAXN * 8];
__device__ __align__(16) float g_h1p[MAXN * 64];   // layer1 out (bias+elu)
__device__ __align__(16) __half2 g_h2h[MAXN * 32]; // layer2 h, fp16
__device__ __align__(16) float g_as2[MAXN];
__device__ __align__(16) float g_ad2[MAXN];
__device__ __align__(16) __half g_wh[256 * 64];    // W1 fp16 [256][64]
__device__ int g_cnt [MAXN];                        // zeroed at END of each call
__device__ int g_cur [MAXN];                        // zeroed at END of each call
__device__ int g_offs[MAXN + 1];
__device__ int g_bsum[64];
__device__ __align__(16) int g_ebuf[MAXE];          // src per CSR slot
__device__ __align__(16) int g_dbuf[MAXE];          // dst per CSR slot
__device__ __align__(16) float g_w2[MAXE];          // layer2 edge weights (CSR order)
__device__ int g_is64;

// ---------------- edge dtype detect -----------------------------------------
__global__ void detect_kernel(const int* __restrict__ ei32, int E) {
    __shared__ int s_or;
    if (threadIdx.x == 0) s_or = 0;
    __syncthreads();
    int acc = 0;
    int nsamp = (E < 4096) ? E : 4096;
    for (int j = threadIdx.x; j < nsamp; j += blockDim.x)
        acc |= ei32[2 * j + 1];
    atomicOr(&s_or, acc);
    __syncthreads();
    if (threadIdx.x == 0) g_is64 = (s_or == 0) ? 1 : 0;
}

// counters consumed this call; zero them for the next call (runs overlapped)
__global__ void reset_kernel(int N) {
    int i = blockIdx.x * blockDim.x + threadIdx.x;
    if (i < N) { g_cnt[i] = 0; g_cur[i] = 0; }
}

// ---------------- W1 -> fp16 -------------------------------------------------
__global__ void wconv_kernel(const float* __restrict__ W1) {
    int i = blockIdx.x * blockDim.x + threadIdx.x;   // 16384
    g_wh[i] = __float2half_rn(W1[i]);
}

__global__ void count_kernel(const void* __restrict__ ei, int E, int N) {
    int i = blockIdx.x * blockDim.x + threadIdx.x;
    if (i >= E) return;
    int d = g_is64 ? (int)((const long long*)ei)[E + i]
                   : ((const int*)ei)[E + i];
    if ((unsigned)d < (unsigned)N) atomicAdd(&g_cnt[d], 1);
}

// ---------------- layer 1 GEMM via WMMA fp16 (HMMA) -------------------------
#define WS_LD 72
#define XS_LD 264
#define OS_LD 72
__global__ void __launch_bounds__(256) gemm1_wmma_kernel(
        const float* __restrict__ x,
        const float* __restrict__ att_s, const float* __restrict__ att_d,
        int N) {
    extern __shared__ char smem[];
    __half* Wsm = (__half*)smem;                     // [256][WS_LD]
    __half* xs  = (__half*)(smem + 36864);           // [128][XS_LD]
    float*  osm = (float*)(smem + 36864);            // aliases xs

    int tid = threadIdx.x;
    int wid = tid >> 5;
    int r0 = blockIdx.x * 128;

    #pragma unroll
    for (int i = 0; i < 8; i++) {
        int idx = tid + i * 256;
        int row = idx >> 3, q = idx & 7;
        *(uint4*)&Wsm[row * WS_LD + q * 8] = ((const uint4*)g_wh)[idx];
    }
    #pragma unroll
    for (int it = 0; it < 32; it++) {
        int idx = tid + it * 256;
        int row = idx >> 6, f4 = idx & 63;
        int grow = r0 + row;
        float4 v = make_float4(0.f, 0.f, 0.f, 0.f);
        if (grow < N) v = ((const float4*)x)[(size_t)grow * 64 + f4];
        __half2 h01 = __floats2half2_rn(v.x, v.y);
        __half2 h23 = __floats2half2_rn(v.z, v.w);
        *(uint2*)&xs[row * XS_LD + f4 * 4] =
            make_uint2(*(uint32_t*)&h01, *(uint32_t*)&h23);
    }
    __syncthreads();

    wmma::fragment<wmma::accumulator, 16, 16, 16, float> c[4];
    #pragma unroll
    for (int n = 0; n < 4; n++) wmma::fill_fragment(c[n], 0.f);

    #pragma unroll
    for (int k16 = 0; k16 < 16; k16++) {
        wmma::fragment<wmma::matrix_a, 16, 16, 16, __half, wmma::row_major> a;
        wmma::load_matrix_sync(a, &xs[wid * 16 * XS_LD + k16 * 16], XS_LD);
        #pragma unroll
        for (int n = 0; n < 4; n++) {
            wmma::fragment<wmma::matrix_b, 16, 16, 16, __half, wmma::row_major> b;
            wmma::load_matrix_sync(b, &Wsm[k16 * 16 * WS_LD + n * 16], WS_LD);
            wmma::mma_sync(c[n], a, b, c[n]);
        }
    }

    __syncthreads();
    #pragma unroll
    for (int n = 0; n < 4; n++)
        wmma::store_matrix_sync(&osm[wid * 16 * OS_LD + n * 16], c[n], OS_LD,
                                wmma::mem_row_major);
    __syncthreads();

    int row = tid >> 1, half = tid & 1;
    int grow = r0 + row;
    if (grow < N) {
        const float* orow = &osm[row * OS_LD + half * 32];
        #pragma unroll
        for (int q = 0; q < 4; q++) {
            __half2 hh[4];
            #pragma unroll
            for (int p = 0; p < 4; p++)
                hh[p] = __floats2half2_rn(orow[q * 8 + p * 2], orow[q * 8 + p * 2 + 1]);
            *(uint4*)(&g_h1h[(size_t)grow * 32 + half * 16 + q * 4]) = *(uint4*)hh;
        }
        #pragma unroll
        for (int hh = 0; hh < 4; hh++) {
            int h = half * 4 + hh;
            float as = 0.f, ad = 0.f;
            #pragma unroll
            for (int j = 0; j < 8; j++) {
                float cv = orow[hh * 8 + j];
                as = fmaf(cv, __ldg(&att_s[h * 8 + j]), as);
                ad = fmaf(cv, __ldg(&att_d[h * 8 + j]), ad);
            }
            g_as1[grow * 8 + h] = as;
            g_ad1[grow * 8 + h] = ad;
        }
    }
}

// ---------------- scan ------------------------------------------------------
__global__ void scan_block_kernel(int N) {
    __shared__ int wsum[32];
    int tid = threadIdx.x, lane = tid & 31, wid = tid >> 5;
    int i = blockIdx.x * 1024 + tid;
    int v = (i < N) ? g_cnt[i] : 0;
    int sc = v;
    #pragma unroll
    for (int o = 1; o < 32; o <<= 1) {
        int t = __shfl_up_sync(0xffffffffu, sc, o);
        if (lane >= o) sc += t;
    }
    if (lane == 31) wsum[wid] = sc;
    __syncthreads();
    if (wid == 0) {
        int s = wsum[lane];
        #pragma unroll
        for (int o = 1; o < 32; o <<= 1) {
            int t = __shfl_up_sync(0xffffffffu, s, o);
            if (lane >= o) s += t;
        }
        wsum[lane] = s;
    }
    __syncthreads();
    int add = (wid > 0) ? wsum[wid - 1] : 0;
    if (i < N) g_offs[i] = add + sc - v;
    if (tid == 0) g_bsum[blockIdx.x] = wsum[31];
}

__global__ void scan_add_kernel(int N, int nb) {
    __shared__ int prefix;
    int b = blockIdx.x;
    int lane = threadIdx.x & 31;
    if (threadIdx.x < 32) {
        int acc = 0;
        for (int j = lane; j < b; j += 32) acc += g_bsum[j];
        #pragma unroll
        for (int o = 16; o >= 1; o >>= 1) acc += __shfl_xor_sync(0xffffffffu, acc, o);
        if (lane == 0) prefix = acc;
    }
    __syncthreads();
    int i = b * 1024 + threadIdx.x;
    if (i < N) g_offs[i] += prefix;
    if (b == nb - 1 && threadIdx.x == 0) g_offs[N] = prefix + g_bsum[b];
}

__global__ void scatter_kernel(const void* __restrict__ ei, int E, int N) {
    int i = blockIdx.x * blockDim.x + threadIdx.x;
    if (i >= E) return;
    int s, d;
    if (g_is64) {
        const long long* e64 = (const long long*)ei;
        s = (int)e64[i]; d = (int)e64[E + i];
    } else {
        const int* e32 = (const int*)ei;
        s = e32[i]; d = e32[E + i];
    }
    if ((unsigned)d < (unsigned)N) {
        int p = atomicAdd(&g_cur[d], 1);
        int pos = g_offs[d] + p;
        g_ebuf[pos] = s;
        g_dbuf[pos] = d;
    }
}

#define LRELU(e) ((e) > 0.f ? (e) : 0.2f * (e))

// layer2 edge weights in CSR order: sequential reads/writes, L2-resident lookups
__global__ void wcalc2_kernel(int E) {
    int i = blockIdx.x * blockDim.x + threadIdx.x;
    if (i >= E) return;
    int s = g_ebuf[i];
    int d = g_dbuf[i];
    g_w2[i] = __expf(LRELU(__ldg(&g_as2[s]) + __ldg(&g_ad2[d])));
}

// ---------------- layer 1 aggregation (R12 form: 1 warp/dst, 8-batch) -------
__global__ void agg1_kernel(const float* __restrict__ bias1, int N) {
    int warp = (blockIdx.x * blockDim.x + threadIdx.x) >> 5;
    int lane = threadIdx.x & 31;
    if (warp >= N) return;
    int dst = warp;
    int head = lane >> 2;
    float ad = g_ad1[dst * 8 + head];
    int beg = g_offs[dst], end = g_offs[dst + 1];

    float den = 0.f, ax = 0.f, ay = 0.f;
    int i = beg;
    for (; i < end && (i & 3); i++) {
        int s = __ldg(&g_ebuf[i]);
        float w = __expf(LRELU(__ldg(&g_as1[s * 8 + head]) + ad));
        float2 hv = __half22float2(__ldg(&g_h1h[(size_t)s * 32 + lane]));
        den += w; ax = fmaf(w, hv.x, ax); ay = fmaf(w, hv.y, ay);
    }
    for (; i + 8 <= end; i += 8) {
        int4 sa = *(const int4*)&g_ebuf[i];
        int4 sb = *(const int4*)&g_ebuf[i + 4];
        float e0 = __ldg(&g_as1[sa.x * 8 + head]);
        float e1 = __ldg(&g_as1[sa.y * 8 + head]);
        float e2 = __ldg(&g_as1[sa.z * 8 + head]);
        float e3 = __ldg(&g_as1[sa.w * 8 + head]);
        float e4 = __ldg(&g_as1[sb.x * 8 + head]);
        float e5 = __ldg(&g_as1[sb.y * 8 + head]);
        float e6 = __ldg(&g_as1[sb.z * 8 + head]);
        float e7 = __ldg(&g_as1[sb.w * 8 + head]);
        __half2 q0 = __ldg(&g_h1h[(size_t)sa.x * 32 + lane]);
        __half2 q1 = __ldg(&g_h1h[(size_t)sa.y * 32 + lane]);
        __half2 q2 = __ldg(&g_h1h[(size_t)sa.z * 32 + lane]);
        __half2 q3 = __ldg(&g_h1h[(size_t)sa.w * 32 + lane]);
        __half2 q4 = __ldg(&g_h1h[(size_t)sb.x * 32 + lane]);
        __half2 q5 = __ldg(&g_h1h[(size_t)sb.y * 32 + lane]);
        __half2 q6 = __ldg(&g_h1h[(size_t)sb.z * 32 + lane]);
        __half2 q7 = __ldg(&g_h1h[(size_t)sb.w * 32 + lane]);
        float w0 = __expf(LRELU(e0 + ad)), w1 = __expf(LRELU(e1 + ad));
        float w2 = __expf(LRELU(e2 + ad)), w3 = __expf(LRELU(e3 + ad));
        float w4 = __expf(LRELU(e4 + ad)), w5 = __expf(LRELU(e5 + ad));
        float w6 = __expf(LRELU(e6 + ad)), w7 = __expf(LRELU(e7 + ad));
        den += ((w0 + w1) + (w2 + w3)) + ((w4 + w5) + (w6 + w7));
        float2 f0 = __half22float2(q0), f1 = __half22float2(q1);
        float2 f2 = __half22float2(q2), f3 = __half22float2(q3);
        float2 f4 = __half22float2(q4), f5 = __half22float2(q5);
        float2 f6 = __half22float2(q6), f7 = __half22float2(q7);
        ax = fmaf(w0, f0.x, ax); ay = fmaf(w0, f0.y, ay);
        ax = fmaf(w1, f1.x, ax); ay = fmaf(w1, f1.y, ay);
        ax = fmaf(w2, f2.x, ax); ay = fmaf(w2, f2.y, ay);
        ax = fmaf(w3, f3.x, ax); ay = fmaf(w3, f3.y, ay);
        ax = fmaf(w4, f4.x, ax); ay = fmaf(w4, f4.y, ay);
        ax = fmaf(w5, f5.x, ax); ay = fmaf(w5, f5.y, ay);
        ax = fmaf(w6, f6.x, ax); ay = fmaf(w6, f6.y, ay);
        ax = fmaf(w7, f7.x, ax); ay = fmaf(w7, f7.y, ay);
    }
    for (; i + 4 <= end; i += 4) {
        int4 ss = *(const int4*)&g_ebuf[i];
        float e0 = __ldg(&g_as1[ss.x * 8 + head]);
        float e1 = __ldg(&g_as1[ss.y * 8 + head]);
        float e2 = __ldg(&g_as1[ss.z * 8 + head]);
        float e3 = __ldg(&g_as1[ss.w * 8 + head]);
        __half2 q0 = __ldg(&g_h1h[(size_t)ss.x * 32 + lane]);
        __half2 q1 = __ldg(&g_h1h[(size_t)ss.y * 32 + lane]);
        __half2 q2 = __ldg(&g_h1h[(size_t)ss.z * 32 + lane]);
        __half2 q3 = __ldg(&g_h1h[(size_t)ss.w * 32 + lane]);
        float w0 = __expf(LRELU(e0 + ad)), w1 = __expf(LRELU(e1 + ad));
        float w2 = __expf(LRELU(e2 + ad)), w3 = __expf(LRELU(e3 + ad));
        den += (w0 + w1) + (w2 + w3);
        float2 f0 = __half22float2(q0), f1 = __half22float2(q1);
        float2 f2 = __half22float2(q2), f3 = __half22float2(q3);
        ax = fmaf(w0, f0.x, ax); ay = fmaf(w0, f0.y, ay);
        ax = fmaf(w1, f1.x, ax); ay = fmaf(w1, f1.y, ay);
        ax = fmaf(w2, f2.x, ax); ay = fmaf(w2, f2.y, ay);
        ax = fmaf(w3, f3.x, ax); ay = fmaf(w3, f3.y, ay);
    }
    for (; i < end; i++) {
        int s = __ldg(&g_ebuf[i]);
        float w = __expf(LRELU(__ldg(&g_as1[s * 8 + head]) + ad));
        float2 hv = __half22float2(__ldg(&g_h1h[(size_t)s * 32 + lane]));
        den += w; ax = fmaf(w, hv.x, ax); ay = fmaf(w, hv.y, ay);
    }
    float inv = 1.f / (den + 1e-16f);
    int c0 = lane * 2;
    float v0 = fmaf(ax, inv, bias1[c0]);
    float v1 = fmaf(ay, inv, bias1[c0 + 1]);
    v0 = (v0 > 0.f) ? v0 : expm1f(v0);
    v1 = (v1 > 0.f) ? v1 : expm1f(v1);
    ((float2*)g_h1p)[(size_t)dst * 32 + lane] = make_float2(v0, v1);
}

// ---------------- layer 2 GEMM ----------------------------------------------
__global__ void gemm2_kernel(const float* __restrict__ W2,
                             const float* __restrict__ att_s2, const float* __restrict__ att_d2,
                             int N) {
    __shared__ float Ws[64 * 64];
    __shared__ float xs[32 * 64];
    int tid = threadIdx.x;

    float4* Ws4 = (float4*)Ws;
    const float4* Wg4 = (const float4*)W2;
    #pragma unroll
    for (int i = 0; i < 4; i++) Ws4[tid + i * 256] = Wg4[tid + i * 256];

    int r0 = blockIdx.x * 32;
    float4* xs4 = (float4*)xs;
    const float4* xg4 = (const float4*)(g_h1p + (size_t)r0 * 64);
    int rows = N - r0; if (rows > 32) rows = 32;
    int nf4 = rows * 16;
    #pragma unroll
    for (int i = 0; i < 2; i++) {
        int idx = tid + i * 256;
        xs4[idx] = (idx < nf4) ? xg4[idx] : make_float4(0.f, 0.f, 0.f, 0.f);
    }
    __syncthreads();

    int r = tid >> 3, cg = tid & 7;
    float acc[8];
    #pragma unroll
    for (int j = 0; j < 8; j++) acc[j] = 0.f;
    const float* xr = xs + r * 64;
    #pragma unroll 8
    for (int k = 0; k < 64; k++) {
        float xv = xr[k];
        float4 w0 = Ws4[k * 16 + cg * 2];
        float4 w1 = Ws4[k * 16 + cg * 2 + 1];
        acc[0] = fmaf(xv, w0.x, acc[0]); acc[1] = fmaf(xv, w0.y, acc[1]);
        acc[2] = fmaf(xv, w0.z, acc[2]); acc[3] = fmaf(xv, w0.w, acc[3]);
        acc[4] = fmaf(xv, w1.x, acc[4]); acc[5] = fmaf(xv, w1.y, acc[5]);
        acc[6] = fmaf(xv, w1.z, acc[6]); acc[7] = fmaf(xv, w1.w, acc[7]);
    }

    float ps = 0.f, pd = 0.f;
    #pragma unroll
    for (int j = 0; j < 8; j++) {
        ps = fmaf(acc[j], att_s2[cg * 8 + j], ps);
        pd = fmaf(acc[j], att_d2[cg * 8 + j], pd);
    }
    #pragma unroll
    for (int o = 4; o >= 1; o >>= 1) {
        ps += __shfl_down_sync(0xffffffffu, ps, o);
        pd += __shfl_down_sync(0xffffffffu, pd, o);
    }

    int row = r0 + r;
    if (row < N) {
        __half2 hh[4];
        #pragma unroll
        for (int cp = 0; cp < 4; cp++)
            hh[cp] = __floats2half2_rn(acc[cp * 2], acc[cp * 2 + 1]);
        *(uint4*)(&g_h2h[(size_t)row * 32 + cg * 4]) = *(uint4*)hh;
        if (cg == 0) { g_as2[row] = ps; g_ad2[row] = pd; }
    }
}

// ---------------- layer 2 aggregation: precomputed weights + log_softmax ----
__global__ void agg2_kernel(const float* __restrict__ bias2, float* __restrict__ out, int N) {
    int warp = (blockIdx.x * blockDim.x + threadIdx.x) >> 5;
    int lane = threadIdx.x & 31;
    if (warp >= N) return;
    int dst = warp;
    int beg = g_offs[dst], end = g_offs[dst + 1];

    float den0 = 0.f, ax0 = 0.f, ay0 = 0.f;
    float den1 = 0.f, ax1 = 0.f, ay1 = 0.f;
    int i = beg;
    for (; i < end && (i & 3); i++) {
        int s = __ldg(&g_ebuf[i]);
        float w = __ldg(&g_w2[i]);
        float2 hv = __half22float2(__ldg(&g_h2h[(size_t)s * 32 + lane]));
        den0 += w; ax0 = fmaf(w, hv.x, ax0); ay0 = fmaf(w, hv.y, ay0);
    }
    for (; i + 8 <= end; i += 8) {
        int4 sa = *(const int4*)&g_ebuf[i];
        int4 sb = *(const int4*)&g_ebuf[i + 4];
        float4 wa = *(const float4*)&g_w2[i];
        float4 wb = *(const float4*)&g_w2[i + 4];
        __half2 q0 = __ldg(&g_h2h[(size_t)sa.x * 32 + lane]);
        __half2 q1 = __ldg(&g_h2h[(size_t)sa.y * 32 + lane]);
        __half2 q2 = __ldg(&g_h2h[(size_t)sa.z * 32 + lane]);
        __half2 q3 = __ldg(&g_h2h[(size_t)sa.w * 32 + lane]);
        __half2 q4 = __ldg(&g_h2h[(size_t)sb.x * 32 + lane]);
        __half2 q5 = __ldg(&g_h2h[(size_t)sb.y * 32 + lane]);
        __half2 q6 = __ldg(&g_h2h[(size_t)sb.z * 32 + lane]);
        __half2 q7 = __ldg(&g_h2h[(size_t)sb.w * 32 + lane]);
        den0 += (wa.x + wa.y) + (wa.z + wa.w);
        den1 += (wb.x + wb.y) + (wb.z + wb.w);
        float2 f0 = __half22float2(q0), f1 = __half22float2(q1);
        float2 f2 = __half22float2(q2), f3 = __half22float2(q3);
        float2 f4 = __half22float2(q4), f5 = __half22float2(q5);
        float2 f6 = __half22float2(q6), f7 = __half22float2(q7);
        ax0 = fmaf(wa.x, f0.x, ax0); ay0 = fmaf(wa.x, f0.y, ay0);
        ax0 = fmaf(wa.y, f1.x, ax0); ay0 = fmaf(wa.y, f1.y, ay0);
        ax0 = fmaf(wa.z, f2.x, ax0); ay0 = fmaf(wa.z, f2.y, ay0);
        ax0 = fmaf(wa.w, f3.x, ax0); ay0 = fmaf(wa.w, f3.y, ay0);
        ax1 = fmaf(wb.x, f4.x, ax1); ay1 = fmaf(wb.x, f4.y, ay1);
        ax1 = fmaf(wb.y, f5.x, ax1); ay1 = fmaf(wb.y, f5.y, ay1);
        ax1 = fmaf(wb.z, f6.x, ax1); ay1 = fmaf(wb.z, f6.y, ay1);
        ax1 = fmaf(wb.w, f7.x, ax1); ay1 = fmaf(wb.w, f7.y, ay1);
    }
    for (; i + 4 <= end; i += 4) {
        int4 ss = *(const int4*)&g_ebuf[i];
        float4 wv = *(const float4*)&g_w2[i];
        __half2 q0 = __ldg(&g_h2h[(size_t)ss.x * 32 + lane]);
        __half2 q1 = __ldg(&g_h2h[(size_t)ss.y * 32 + lane]);
        __half2 q2 = __ldg(&g_h2h[(size_t)ss.z * 32 + lane]);
        __half2 q3 = __ldg(&g_h2h[(size_t)ss.w * 32 + lane]);
        den0 += (wv.x + wv.y) + (wv.z + wv.w);
        float2 f0 = __half22float2(q0), f1 = __half22float2(q1);
        float2 f2 = __half22float2(q2), f3 = __half22float2(q3);
        ax0 = fmaf(wv.x, f0.x, ax0); ay0 = fmaf(wv.x, f0.y, ay0);
        ax1 = fmaf(wv.y, f1.x, ax1); ay1 = fmaf(wv.y, f1.y, ay1);
        ax0 = fmaf(wv.z, f2.x, ax0); ay0 = fmaf(wv.z, f2.y, ay0);
        ax1 = fmaf(wv.w, f3.x, ax1); ay1 = fmaf(wv.w, f3.y, ay1);
    }
    for (; i < end; i++) {
        int s = __ldg(&g_ebuf[i]);
        float w = __ldg(&g_w2[i]);
        float2 hv = __half22float2(__ldg(&g_h2h[(size_t)s * 32 + lane]));
        den0 += w; ax0 = fmaf(w, hv.x, ax0); ay0 = fmaf(w, hv.y, ay0);
    }

    float den = den0 + den1;
    float ax = ax0 + ax1, ay = ay0 + ay1;
    float inv = 1.f / (den + 1e-16f);
    int c0 = lane * 2;
    float v0 = fmaf(ax, inv, bias2[c0]);
    float v1 = fmaf(ay, inv, bias2[c0 + 1]);

    float m = fmaxf(v0, v1);
    #pragma unroll
    for (int o = 16; o >= 1; o >>= 1) m = fmaxf(m, __shfl_xor_sync(0xffffffffu, m, o));
    float se = __expf(v0 - m) + __expf(v1 - m);
    #pragma unroll
    for (int o = 16; o >= 1; o >>= 1) se += __shfl_xor_sync(0xffffffffu, se, o);
    float lse = m + logf(se);

    ((float2*)out)[(size_t)dst * 32 + lane] = make_float2(v0 - lse, v1 - lse);
}

// ---------------- launch ----------------------------------------------------
extern "C" void kernel_launch(void* const* d_in, const int* in_sizes, int n_in,
                              void* d_out, int out_size) {
    const float* x      = (const float*)d_in[0];
    const void*  ei     = d_in[1];
    const float* W1     = (const float*)d_in[2];
    const float* atts1  = (const float*)d_in[3];
    const float* attd1  = (const float*)d_in[4];
    const float* bias1  = (const float*)d_in[5];
    const float* W2     = (const float*)d_in[6];
    const float* atts2  = (const float*)d_in[7];
    const float* attd2  = (const float*)d_in[8];
    const float* bias2  = (const float*)d_in[9];
    float* out = (float*)d_out;

    int N = in_sizes[0] / 256;
    int E = in_sizes[1] / 2;
    int nb = (N + 1023) / 1024;

    static cudaStream_t s2 = nullptr;
    static cudaEvent_t evRoot = nullptr, evG = nullptr, evS = nullptr, evR = nullptr;
    if (s2 == nullptr) {
        cudaStreamCreateWithFlags(&s2, cudaStreamNonBlocking);
        cudaEventCreateWithFlags(&evRoot, cudaEventDisableTiming);
        cudaEventCreateWithFlags(&evG, cudaEventDisableTiming);
        cudaEventCreateWithFlags(&evS, cudaEventDisableTiming);
        cudaEventCreateWithFlags(&evR, cudaEventDisableTiming);
        cudaFuncSetAttribute(gemm1_wmma_kernel,
                             cudaFuncAttributeMaxDynamicSharedMemorySize, 104448);
    }

    // fork: GEMM chain on s2, CSR chain on the main stream.
    cudaEventRecord(evRoot, 0);
    cudaStreamWaitEvent(s2, evRoot, 0);

    wconv_kernel     <<<64, 256, 0, s2>>>(W1);
    gemm1_wmma_kernel<<<(N + 127) / 128, 256, 104448, s2>>>(x, atts1, attd1, N);
    cudaEventRecord(evG, s2);

    detect_kernel    <<<1, 256>>>((const int*)ei, E);
    count_kernel     <<<(E + 255) / 256, 256>>>(ei, E, N);
    scan_block_kernel<<<nb, 1024>>>(N);
    scan_add_kernel  <<<nb, 1024>>>(N, nb);
    scatter_kernel   <<<(E + 255) / 256, 256>>>(ei, E, N);
    cudaEventRecord(evS, 0);

    // counter reset for the next call — overlapped with the agg/gemm2 tail
    cudaStreamWaitEvent(s2, evS, 0);
    reset_kernel<<<(N + 255) / 256, 256, 0, s2>>>(N);
    cudaEventRecord(evR, s2);

    // join: agg1 needs both chains
    cudaStreamWaitEvent(0, evG, 0);
    agg1_kernel  <<<(N + 7) / 8, 256>>>(bias1, N);
    gemm2_kernel <<<(N + 31) / 32, 256>>>(W2, atts2, attd2, N);
    wcalc2_kernel<<<(E + 255) / 256, 256>>>(E);
    agg2_kernel  <<<(N + 7) / 8, 256>>>(bias2, out, N);

    // rejoin s2 before capture ends
    cudaStreamWaitEvent(0, evR, 0);
}

// round 15
// speedup vs baseline: 1.3992x; 1.3154x over previous
#include <cuda_runtime.h>
#include <cuda_fp16.h>
#include <mma.h>
#include <math.h>
#include <cstdint>

#define MAXN 50000
#define MAXE 1600000

using namespace nvcuda;

// ---------------- device scratch (zero-initialized at module load) ----------
__device__ __align__(16) __half2 g_h1h[MAXN * 32];  // layer1 h, fp16 [N,64]
__device__ __align__(16) float g_as1[MAXN * 8];
__device__ __align__(16) float g_ad1[MAXN * 8];
__device__ __align__(16) __half2 g_h1ph[MAXN * 32]; // layer1 out (bias+elu), fp16
__device__ __align__(16) __half2 g_h2h[MAXN * 32];  // layer2 h, fp16
__device__ __align__(16) float g_as2[MAXN];
__device__ __align__(16) float g_ad2[MAXN];
__device__ __align__(16) __half g_wh[256 * 64];     // W1 fp16 [256][64]
__device__ int g_cnt [MAXN];                         // zeroed at END of each call
__device__ int g_cur [MAXN];                         // zeroed at END of each call
__device__ int g_offs[MAXN + 1];
__device__ int g_bsum[64];
__device__ __align__(16) int g_ebuf[MAXE];           // src per CSR slot
__device__ __align__(16) float g_w2[MAXE];           // layer2 edge weights (CSR order)

#define LRELU(e) ((e) > 0.f ? (e) : 0.2f * (e))

// per-block dtype detect: first 32 odd 32-bit words are all zero iff int64
__device__ __forceinline__ int block_is64(const int* e32, int E, int* s_flag) {
    if (threadIdx.x < 32) {
        int v = (threadIdx.x < E) ? e32[2 * threadIdx.x + 1] : 0;
        unsigned nz = __ballot_sync(0xffffffffu, v != 0);
        if (threadIdx.x == 0) *s_flag = (nz == 0u) ? 1 : 0;
    }
    __syncthreads();
    return *s_flag;
}

// counters consumed this call; zero them for the next call (runs overlapped)
__global__ void reset_kernel(int N) {
    int i = blockIdx.x * blockDim.x + threadIdx.x;
    if (i < N) { g_cnt[i] = 0; g_cur[i] = 0; }
}

// ---------------- W1 -> fp16 -------------------------------------------------
__global__ void wconv_kernel(const float* __restrict__ W1) {
    int i = blockIdx.x * blockDim.x + threadIdx.x;   // 16384
    g_wh[i] = __float2half_rn(W1[i]);
}

__global__ void count_kernel(const void* __restrict__ ei, int E, int N) {
    __shared__ int s_is64;
    int is64 = block_is64((const int*)ei, E, &s_is64);
    int i = blockIdx.x * blockDim.x + threadIdx.x;
    if (i >= E) return;
    int d = is64 ? (int)((const long long*)ei)[E + i]
                 : ((const int*)ei)[E + i];
    if ((unsigned)d < (unsigned)N) atomicAdd(&g_cnt[d], 1);
}

// ---------------- layer 1 GEMM via WMMA fp16 (HMMA) -------------------------
#define WS_LD 72
#define XS_LD 264
#define OS_LD 72
__global__ void __launch_bounds__(256) gemm1_wmma_kernel(
        const float* __restrict__ x,
        const float* __restrict__ att_s, const float* __restrict__ att_d,
        int N) {
    extern __shared__ char smem[];
    __half* Wsm = (__half*)smem;                     // [256][WS_LD]
    __half* xs  = (__half*)(smem + 36864);           // [128][XS_LD]
    float*  osm = (float*)(smem + 36864);            // aliases xs

    int tid = threadIdx.x;
    int wid = tid >> 5;
    int r0 = blockIdx.x * 128;

    #pragma unroll
    for (int i = 0; i < 8; i++) {
        int idx = tid + i * 256;
        int row = idx >> 3, q = idx & 7;
        *(uint4*)&Wsm[row * WS_LD + q * 8] = ((const uint4*)g_wh)[idx];
    }
    #pragma unroll
    for (int it = 0; it < 32; it++) {
        int idx = tid + it * 256;
        int row = idx >> 6, f4 = idx & 63;
        int grow = r0 + row;
        float4 v = make_float4(0.f, 0.f, 0.f, 0.f);
        if (grow < N) v = ((const float4*)x)[(size_t)grow * 64 + f4];
        __half2 h01 = __floats2half2_rn(v.x, v.y);
        __half2 h23 = __floats2half2_rn(v.z, v.w);
        *(uint2*)&xs[row * XS_LD + f4 * 4] =
            make_uint2(*(uint32_t*)&h01, *(uint32_t*)&h23);
    }
    __syncthreads();

    wmma::fragment<wmma::accumulator, 16, 16, 16, float> c[4];
    #pragma unroll
    for (int n = 0; n < 4; n++) wmma::fill_fragment(c[n], 0.f);

    #pragma unroll
    for (int k16 = 0; k16 < 16; k16++) {
        wmma::fragment<wmma::matrix_a, 16, 16, 16, __half, wmma::row_major> a;
        wmma::load_matrix_sync(a, &xs[wid * 16 * XS_LD + k16 * 16], XS_LD);
        #pragma unroll
        for (int n = 0; n < 4; n++) {
            wmma::fragment<wmma::matrix_b, 16, 16, 16, __half, wmma::row_major> b;
            wmma::load_matrix_sync(b, &Wsm[k16 * 16 * WS_LD + n * 16], WS_LD);
            wmma::mma_sync(c[n], a, b, c[n]);
        }
    }

    __syncthreads();
    #pragma unroll
    for (int n = 0; n < 4; n++)
        wmma::store_matrix_sync(&osm[wid * 16 * OS_LD + n * 16], c[n], OS_LD,
                                wmma::mem_row_major);
    __syncthreads();

    int row = tid >> 1, half = tid & 1;
    int grow = r0 + row;
    if (grow < N) {
        const float* orow = &osm[row * OS_LD + half * 32];
        #pragma unroll
        for (int q = 0; q < 4; q++) {
            __half2 hh[4];
            #pragma unroll
            for (int p = 0; p < 4; p++)
                hh[p] = __floats2half2_rn(orow[q * 8 + p * 2], orow[q * 8 + p * 2 + 1]);
            *(uint4*)(&g_h1h[(size_t)grow * 32 + half * 16 + q * 4]) = *(uint4*)hh;
        }
        #pragma unroll
        for (int hh = 0; hh < 4; hh++) {
            int h = half * 4 + hh;
            float as = 0.f, ad = 0.f;
            #pragma unroll
            for (int j = 0; j < 8; j++) {
                float cv = orow[hh * 8 + j];
                as = fmaf(cv, __ldg(&att_s[h * 8 + j]), as);
                ad = fmaf(cv, __ldg(&att_d[h * 8 + j]), ad);
            }
            g_as1[grow * 8 + h] = as;
            g_ad1[grow * 8 + h] = ad;
        }
    }
}

// ---------------- scan ------------------------------------------------------
__global__ void scan_block_kernel(int N) {
    __shared__ int wsum[32];
    int tid = threadIdx.x, lane = tid & 31, wid = tid >> 5;
    int i = blockIdx.x * 1024 + tid;
    int v = (i < N) ? g_cnt[i] : 0;
    int sc = v;
    #pragma unroll
    for (int o = 1; o < 32; o <<= 1) {
        int t = __shfl_up_sync(0xffffffffu, sc, o);
        if (lane >= o) sc += t;
    }
    if (lane == 31) wsum[wid] = sc;
    __syncthreads();
    if (wid == 0) {
        int s = wsum[lane];
        #pragma unroll
        for (int o = 1; o < 32; o <<= 1) {
            int t = __shfl_up_sync(0xffffffffu, s, o);
            if (lane >= o) s += t;
        }
        wsum[lane] = s;
    }
    __syncthreads();
    int add = (wid > 0) ? wsum[wid - 1] : 0;
    if (i < N) g_offs[i] = add + sc - v;
    if (tid == 0) g_bsum[blockIdx.x] = wsum[31];
}

__global__ void scan_add_kernel(int N, int nb) {
    __shared__ int prefix;
    int b = blockIdx.x;
    int lane = threadIdx.x & 31;
    if (threadIdx.x < 32) {
        int acc = 0;
        for (int j = lane; j < b; j += 32) acc += g_bsum[j];
        #pragma unroll
        for (int o = 16; o >= 1; o >>= 1) acc += __shfl_xor_sync(0xffffffffu, acc, o);
        if (lane == 0) prefix = acc;
    }
    __syncthreads();
    int i = b * 1024 + threadIdx.x;
    if (i < N) g_offs[i] += prefix;
    if (b == nb - 1 && threadIdx.x == 0) g_offs[N] = prefix + g_bsum[b];
}

__global__ void scatter_kernel(const void* __restrict__ ei, int E, int N) {
    __shared__ int s_is64;
    int is64 = block_is64((const int*)ei, E, &s_is64);
    int i = blockIdx.x * blockDim.x + threadIdx.x;
    if (i >= E) return;
    int s, d;
    if (is64) {
        const long long* e64 = (const long long*)ei;
        s = (int)e64[i]; d = (int)e64[E + i];
    } else {
        const int* e32 = (const int*)ei;
        s = e32[i]; d = e32[E + i];
    }
    if ((unsigned)d < (unsigned)N) {
        int p = atomicAdd(&g_cur[d], 1);
        g_ebuf[g_offs[d] + p] = s;
    }
}

// layer2 edge weights, warp per dst (dst implicit in CSR row)
__global__ void wcalc2_kernel(int N) {
    int warp = (blockIdx.x * blockDim.x + threadIdx.x) >> 5;
    int lane = threadIdx.x & 31;
    if (warp >= N) return;
    float ad = g_ad2[warp];
    int beg = g_offs[warp], end = g_offs[warp + 1];
    for (int i = beg + lane; i < end; i += 32) {
        int s = __ldg(&g_ebuf[i]);
        g_w2[i] = __expf(LRELU(__ldg(&g_as2[s]) + ad));
    }
}

// ---------------- layer 1 aggregation (1 warp/dst, 8-batch) ------------------
__global__ void agg1_kernel(const float* __restrict__ bias1, int N) {
    int warp = (blockIdx.x * blockDim.x + threadIdx.x) >> 5;
    int lane = threadIdx.x & 31;
    if (warp >= N) return;
    int dst = warp;
    int head = lane >> 2;
    float ad = g_ad1[dst * 8 + head];
    int beg = g_offs[dst], end = g_offs[dst + 1];

    float den = 0.f, ax = 0.f, ay = 0.f;
    int i = beg;
    for (; i < end && (i & 3); i++) {
        int s = __ldg(&g_ebuf[i]);
        float w = __expf(LRELU(__ldg(&g_as1[s * 8 + head]) + ad));
        float2 hv = __half22float2(__ldg(&g_h1h[(size_t)s * 32 + lane]));
        den += w; ax = fmaf(w, hv.x, ax); ay = fmaf(w, hv.y, ay);
    }
    for (; i + 8 <= end; i += 8) {
        int4 sa = *(const int4*)&g_ebuf[i];
        int4 sb = *(const int4*)&g_ebuf[i + 4];
        float e0 = __ldg(&g_as1[sa.x * 8 + head]);
        float e1 = __ldg(&g_as1[sa.y * 8 + head]);
        float e2 = __ldg(&g_as1[sa.z * 8 + head]);
        float e3 = __ldg(&g_as1[sa.w * 8 + head]);
        float e4 = __ldg(&g_as1[sb.x * 8 + head]);
        float e5 = __ldg(&g_as1[sb.y * 8 + head]);
        float e6 = __ldg(&g_as1[sb.z * 8 + head]);
        float e7 = __ldg(&g_as1[sb.w * 8 + head]);
        __half2 q0 = __ldg(&g_h1h[(size_t)sa.x * 32 + lane]);
        __half2 q1 = __ldg(&g_h1h[(size_t)sa.y * 32 + lane]);
        __half2 q2 = __ldg(&g_h1h[(size_t)sa.z * 32 + lane]);
        __half2 q3 = __ldg(&g_h1h[(size_t)sa.w * 32 + lane]);
        __half2 q4 = __ldg(&g_h1h[(size_t)sb.x * 32 + lane]);
        __half2 q5 = __ldg(&g_h1h[(size_t)sb.y * 32 + lane]);
        __half2 q6 = __ldg(&g_h1h[(size_t)sb.z * 32 + lane]);
        __half2 q7 = __ldg(&g_h1h[(size_t)sb.w * 32 + lane]);
        float w0 = __expf(LRELU(e0 + ad)), w1 = __expf(LRELU(e1 + ad));
        float w2 = __expf(LRELU(e2 + ad)), w3 = __expf(LRELU(e3 + ad));
        float w4 = __expf(LRELU(e4 + ad)), w5 = __expf(LRELU(e5 + ad));
        float w6 = __expf(LRELU(e6 + ad)), w7 = __expf(LRELU(e7 + ad));
        den += ((w0 + w1) + (w2 + w3)) + ((w4 + w5) + (w6 + w7));
        float2 f0 = __half22float2(q0), f1 = __half22float2(q1);
        float2 f2 = __half22float2(q2), f3 = __half22float2(q3);
        float2 f4 = __half22float2(q4), f5 = __half22float2(q5);
        float2 f6 = __half22float2(q6), f7 = __half22float2(q7);
        ax = fmaf(w0, f0.x, ax); ay = fmaf(w0, f0.y, ay);
        ax = fmaf(w1, f1.x, ax); ay = fmaf(w1, f1.y, ay);
        ax = fmaf(w2, f2.x, ax); ay = fmaf(w2, f2.y, ay);
        ax = fmaf(w3, f3.x, ax); ay = fmaf(w3, f3.y, ay);
        ax = fmaf(w4, f4.x, ax); ay = fmaf(w4, f4.y, ay);
        ax = fmaf(w5, f5.x, ax); ay = fmaf(w5, f5.y, ay);
        ax = fmaf(w6, f6.x, ax); ay = fmaf(w6, f6.y, ay);
        ax = fmaf(w7, f7.x, ax); ay = fmaf(w7, f7.y, ay);
    }
    for (; i + 4 <= end; i += 4) {
        int4 ss = *(const int4*)&g_ebuf[i];
        float e0 = __ldg(&g_as1[ss.x * 8 + head]);
        float e1 = __ldg(&g_as1[ss.y * 8 + head]);
        float e2 = __ldg(&g_as1[ss.z * 8 + head]);
        float e3 = __ldg(&g_as1[ss.w * 8 + head]);
        __half2 q0 = __ldg(&g_h1h[(size_t)ss.x * 32 + lane]);
        __half2 q1 = __ldg(&g_h1h[(size_t)ss.y * 32 + lane]);
        __half2 q2 = __ldg(&g_h1h[(size_t)ss.z * 32 + lane]);
        __half2 q3 = __ldg(&g_h1h[(size_t)ss.w * 32 + lane]);
        float w0 = __expf(LRELU(e0 + ad)), w1 = __expf(LRELU(e1 + ad));
        float w2 = __expf(LRELU(e2 + ad)), w3 = __expf(LRELU(e3 + ad));
        den += (w0 + w1) + (w2 + w3);
        float2 f0 = __half22float2(q0), f1 = __half22float2(q1);
        float2 f2 = __half22float2(q2), f3 = __half22float2(q3);
        ax = fmaf(w0, f0.x, ax); ay = fmaf(w0, f0.y, ay);
        ax = fmaf(w1, f1.x, ax); ay = fmaf(w1, f1.y, ay);
        ax = fmaf(w2, f2.x, ax); ay = fmaf(w2, f2.y, ay);
        ax = fmaf(w3, f3.x, ax); ay = fmaf(w3, f3.y, ay);
    }
    for (; i < end; i++) {
        int s = __ldg(&g_ebuf[i]);
        float w = __expf(LRELU(__ldg(&g_as1[s * 8 + head]) + ad));
        float2 hv = __half22float2(__ldg(&g_h1h[(size_t)s * 32 + lane]));
        den += w; ax = fmaf(w, hv.x, ax); ay = fmaf(w, hv.y, ay);
    }
    float inv = 1.f / (den + 1e-16f);
    int c0 = lane * 2;
    float v0 = fmaf(ax, inv, bias1[c0]);
    float v1 = fmaf(ay, inv, bias1[c0 + 1]);
    v0 = (v0 > 0.f) ? v0 : expm1f(v0);
    v1 = (v1 > 0.f) ? v1 : expm1f(v1);
    g_h1ph[(size_t)dst * 32 + lane] = __floats2half2_rn(v0, v1);
}

// ---------------- layer 2 GEMM via WMMA fp16 --------------------------------
// 128 rows x 64 cols per block, K=64. W2 converted fp32->fp16 in-kernel.
#define W2_LD 72
#define X2_LD 72
__global__ void __launch_bounds__(256) gemm2_wmma_kernel(
        const float* __restrict__ W2,
        const float* __restrict__ att_s2, const float* __restrict__ att_d2,
        int N) {
    extern __shared__ char sm2[];
    __half* Wsm = (__half*)sm2;                  // [64][W2_LD] = 9216B
    __half* xs  = (__half*)(sm2 + 9216);         // [128][X2_LD] halfs = 18432B
    float*  osm = (float*)(sm2 + 9216);          // [128][W2_LD] floats (aliases xs)

    int tid = threadIdx.x;
    int wid = tid >> 5;
    int r0 = blockIdx.x * 128;

    // W2 fp32 [64][64] -> fp16 padded smem
    #pragma unroll
    for (int i = 0; i < 16; i++) {
        int idx = tid + i * 256;                 // 0..4095
        int row = idx >> 6, col = idx & 63;
        Wsm[row * W2_LD + col] = __float2half_rn(W2[idx]);
    }
    // x = h1p fp16 rows
    #pragma unroll
    for (int i = 0; i < 4; i++) {
        int idx = tid + i * 256;                 // 0..1023 uint4 (8 halfs)
        int row = idx >> 3, q = idx & 7;
        int grow = r0 + row;
        uint4 v = make_uint4(0u, 0u, 0u, 0u);
        if (grow < N) v = ((const uint4*)g_h1ph)[(size_t)grow * 8 + q];
        *(uint4*)&xs[row * X2_LD + q * 8] = v;
    }
    __syncthreads();

    wmma::fragment<wmma::accumulator, 16, 16, 16, float> c[4];
    #pragma unroll
    for (int n = 0; n < 4; n++) wmma::fill_fragment(c[n], 0.f);

    #pragma unroll
    for (int k16 = 0; k16 < 4; k16++) {
        wmma::fragment<wmma::matrix_a, 16, 16, 16, __half, wmma::row_major> a;
        wmma::load_matrix_sync(a, &xs[wid * 16 * X2_LD + k16 * 16], X2_LD);
        #pragma unroll
        for (int n = 0; n < 4; n++) {
            wmma::fragment<wmma::matrix_b, 16, 16, 16, __half, wmma::row_major> b;
            wmma::load_matrix_sync(b, &Wsm[k16 * 16 * W2_LD + n * 16], W2_LD);
            wmma::mma_sync(c[n], a, b, c[n]);
        }
    }

    __syncthreads();
    #pragma unroll
    for (int n = 0; n < 4; n++)
        wmma::store_matrix_sync(&osm[wid * 16 * W2_LD + n * 16], c[n], W2_LD,
                                wmma::mem_row_major);
    __syncthreads();

    int row = tid >> 1, half = tid & 1;
    int grow = r0 + row;
    if (grow < N) {
        const float* orow = &osm[row * W2_LD + half * 32];
        #pragma unroll
        for (int q = 0; q < 4; q++) {
            __half2 hh[4];
            #pragma unroll
            for (int p = 0; p < 4; p++)
                hh[p] = __floats2half2_rn(orow[q * 8 + p * 2], orow[q * 8 + p * 2 + 1]);
            *(uint4*)(&g_h2h[(size_t)grow * 32 + half * 16 + q * 4]) = *(uint4*)hh;
        }
        // attention partials over this thread's 32 cols, combine with partner
        float ps = 0.f, pd = 0.f;
        #pragma unroll
        for (int j = 0; j < 32; j++) {
            float cv = orow[j];
            ps = fmaf(cv, __ldg(&att_s2[half * 32 + j]), ps);
            pd = fmaf(cv, __ldg(&att_d2[half * 32 + j]), pd);
        }
        ps += __shfl_xor_sync(0xffffffffu, ps, 1);
        pd += __shfl_xor_sync(0xffffffffu, pd, 1);
        if (half == 0) { g_as2[grow] = ps; g_ad2[grow] = pd; }
    }
}

// ---------------- layer 2 aggregation: precomputed weights + log_softmax ----
__global__ void agg2_kernel(const float* __restrict__ bias2, float* __restrict__ out, int N) {
    int warp = (blockIdx.x * blockDim.x + threadIdx.x) >> 5;
    int lane = threadIdx.x & 31;
    if (warp >= N) return;
    int dst = warp;
    int beg = g_offs[dst], end = g_offs[dst + 1];

    float den0 = 0.f, ax0 = 0.f, ay0 = 0.f;
    float den1 = 0.f, ax1 = 0.f, ay1 = 0.f;
    int i = beg;
    for (; i < end && (i & 3); i++) {
        int s = __ldg(&g_ebuf[i]);
        float w = __ldg(&g_w2[i]);
        float2 hv = __half22float2(__ldg(&g_h2h[(size_t)s * 32 + lane]));
        den0 += w; ax0 = fmaf(w, hv.x, ax0); ay0 = fmaf(w, hv.y, ay0);
    }
    for (; i + 8 <= end; i += 8) {
        int4 sa = *(const int4*)&g_ebuf[i];
        int4 sb = *(const int4*)&g_ebuf[i + 4];
        float4 wa = *(const float4*)&g_w2[i];
        float4 wb = *(const float4*)&g_w2[i + 4];
        __half2 q0 = __ldg(&g_h2h[(size_t)sa.x * 32 + lane]);
        __half2 q1 = __ldg(&g_h2h[(size_t)sa.y * 32 + lane]);
        __half2 q2 = __ldg(&g_h2h[(size_t)sa.z * 32 + lane]);
        __half2 q3 = __ldg(&g_h2h[(size_t)sa.w * 32 + lane]);
        __half2 q4 = __ldg(&g_h2h[(size_t)sb.x * 32 + lane]);
        __half2 q5 = __ldg(&g_h2h[(size_t)sb.y * 32 + lane]);
        __half2 q6 = __ldg(&g_h2h[(size_t)sb.z * 32 + lane]);
        __half2 q7 = __ldg(&g_h2h[(size_t)sb.w * 32 + lane]);
        den0 += (wa.x + wa.y) + (wa.z + wa.w);
        den1 += (wb.x + wb.y) + (wb.z + wb.w);
        float2 f0 = __half22float2(q0), f1 = __half22float2(q1);
        float2 f2 = __half22float2(q2), f3 = __half22float2(q3);
        float2 f4 = __half22float2(q4), f5 = __half22float2(q5);
        float2 f6 = __half22float2(q6), f7 = __half22float2(q7);
        ax0 = fmaf(wa.x, f0.x, ax0); ay0 = fmaf(wa.x, f0.y, ay0);
        ax0 = fmaf(wa.y, f1.x, ax0); ay0 = fmaf(wa.y, f1.y, ay0);
        ax0 = fmaf(wa.z, f2.x, ax0); ay0 = fmaf(wa.z, f2.y, ay0);
        ax0 = fmaf(wa.w, f3.x, ax0); ay0 = fmaf(wa.w, f3.y, ay0);
        ax1 = fmaf(wb.x, f4.x, ax1); ay1 = fmaf(wb.x, f4.y, ay1);
        ax1 = fmaf(wb.y, f5.x, ax1); ay1 = fmaf(wb.y, f5.y, ay1);
        ax1 = fmaf(wb.z, f6.x, ax1); ay1 = fmaf(wb.z, f6.y, ay1);
        ax1 = fmaf(wb.w, f7.x, ax1); ay1 = fmaf(wb.w, f7.y, ay1);
    }
    for (; i + 4 <= end; i += 4) {
        int4 ss = *(const int4*)&g_ebuf[i];
        float4 wv = *(const float4*)&g_w2[i];
        __half2 q0 = __ldg(&g_h2h[(size_t)ss.x * 32 + lane]);
        __half2 q1 = __ldg(&g_h2h[(size_t)ss.y * 32 + lane]);
        __half2 q2 = __ldg(&g_h2h[(size_t)ss.z * 32 + lane]);
        __half2 q3 = __ldg(&g_h2h[(size_t)ss.w * 32 + lane]);
        den0 += (wv.x + wv.y) + (wv.z + wv.w);
        float2 f0 = __half22float2(q0), f1 = __half22float2(q1);
        float2 f2 = __half22float2(q2), f3 = __half22float2(q3);
        ax0 = fmaf(wv.x, f0.x, ax0); ay0 = fmaf(wv.x, f0.y, ay0);
        ax1 = fmaf(wv.y, f1.x, ax1); ay1 = fmaf(wv.y, f1.y, ay1);
        ax0 = fmaf(wv.z, f2.x, ax0); ay0 = fmaf(wv.z, f2.y, ay0);
        ax1 = fmaf(wv.w, f3.x, ax1); ay1 = fmaf(wv.w, f3.y, ay1);
    }
    for (; i < end; i++) {
        int s = __ldg(&g_ebuf[i]);
        float w = __ldg(&g_w2[i]);
        float2 hv = __half22float2(__ldg(&g_h2h[(size_t)s * 32 + lane]));
        den0 += w; ax0 = fmaf(w, hv.x, ax0); ay0 = fmaf(w, hv.y, ay0);
    }

    float den = den0 + den1;
    float ax = ax0 + ax1, ay = ay0 + ay1;
    float inv = 1.f / (den + 1e-16f);
    int c0 = lane * 2;
    float v0 = fmaf(ax, inv, bias2[c0]);
    float v1 = fmaf(ay, inv, bias2[c0 + 1]);

    float m = fmaxf(v0, v1);
    #pragma unroll
    for (int o = 16; o >= 1; o >>= 1) m = fmaxf(m, __shfl_xor_sync(0xffffffffu, m, o));
    float se = __expf(v0 - m) + __expf(v1 - m);
    #pragma unroll
    for (int o = 16; o >= 1; o >>= 1) se += __shfl_xor_sync(0xffffffffu, se, o);
    float lse = m + logf(se);

    ((float2*)out)[(size_t)dst * 32 + lane] = make_float2(v0 - lse, v1 - lse);
}

// ---------------- launch ----------------------------------------------------
extern "C" void kernel_launch(void* const* d_in, const int* in_sizes, int n_in,
                              void* d_out, int out_size) {
    const float* x      = (const float*)d_in[0];
    const void*  ei     = d_in[1];
    const float* W1     = (const float*)d_in[2];
    const float* atts1  = (const float*)d_in[3];
    const float* attd1  = (const float*)d_in[4];
    const float* bias1  = (const float*)d_in[5];
    const float* W2     = (const float*)d_in[6];
    const float* atts2  = (const float*)d_in[7];
    const float* attd2  = (const float*)d_in[8];
    const float* bias2  = (const float*)d_in[9];
    float* out = (float*)d_out;

    int N = in_sizes[0] / 256;
    int E = in_sizes[1] / 2;
    int nb = (N + 1023) / 1024;

    static cudaStream_t s2 = nullptr;
    static cudaEvent_t evRoot = nullptr, evG = nullptr, evS = nullptr, evR = nullptr;
    if (s2 == nullptr) {
        cudaStreamCreateWithFlags(&s2, cudaStreamNonBlocking);
        cudaEventCreateWithFlags(&evRoot, cudaEventDisableTiming);
        cudaEventCreateWithFlags(&evG, cudaEventDisableTiming);
        cudaEventCreateWithFlags(&evS, cudaEventDisableTiming);
        cudaEventCreateWithFlags(&evR, cudaEventDisableTiming);
        cudaFuncSetAttribute(gemm1_wmma_kernel,
                             cudaFuncAttributeMaxDynamicSharedMemorySize, 104448);
    }

    // fork: GEMM chain on s2, CSR chain on the main stream.
    cudaEventRecord(evRoot, 0);
    cudaStreamWaitEvent(s2, evRoot, 0);

    wconv_kernel     <<<64, 256, 0, s2>>>(W1);
    gemm1_wmma_kernel<<<(N + 127) / 128, 256, 104448, s2>>>(x, atts1, attd1, N);
    cudaEventRecord(evG, s2);

    count_kernel     <<<(E + 255) / 256, 256>>>(ei, E, N);
    scan_block_kernel<<<nb, 1024>>>(N);
    scan_add_kernel  <<<nb, 1024>>>(N, nb);
    scatter_kernel   <<<(E + 255) / 256, 256>>>(ei, E, N);
    cudaEventRecord(evS, 0);

    // counter reset for the next call — overlapped with the agg/gemm2 tail
    cudaStreamWaitEvent(s2, evS, 0);
    reset_kernel<<<(N + 255) / 256, 256, 0, s2>>>(N);
    cudaEventRecord(evR, s2);

    // join: agg1 needs both chains
    cudaStreamWaitEvent(0, evG, 0);
    agg1_kernel      <<<(N + 7) / 8, 256>>>(bias1, N);
    gemm2_wmma_kernel<<<(N + 127) / 128, 256, 46080>>>(W2, atts2, attd2, N);
    wcalc2_kernel    <<<(N + 7) / 8, 256>>>(N);
    agg2_kernel      <<<(N + 7) / 8, 256>>>(bias2, out, N);

    // rejoin s2 before capture ends
    cudaStreamWaitEvent(0, evR, 0);
}